// round 9
// baseline (speedup 1.0000x reference)
#include <cuda_runtime.h>
#include <cuda_fp16.h>

// Fixed problem shapes
#define N_NODES   2048
#define N_CHILD   4096
#define NNZ_PER   32768
#define NNZ_TOT   (2 * NNZ_PER)
#define G         8                 // samples per tile
#define NTHREADS  1024
#define NWARPS    (NTHREADS / 32)   // 32
#define NGROUPS   (N_NODES / 32)    // 64
#define NPASS     (NGROUPS / NWARPS) // 2
#define MAXPAD    96                // group max ~55; margin; mult of 4
#define PAD_ENTRIES (NGROUPS * 32 * MAXPAD)
#define NCTAS     148               // 1 CTA / SM (128 KB smem)

// ---------------- static device scratch -------------------------------------
// SELL-32, 4-packed: group g, lane l, entry j lives at
//   g*32*MAXPAD + (j>>2)*128 + l*4 + (j&3)
__device__ unsigned g_pad[PAD_ENTRIES];  // (col<<16)|fp16(exp(w)), 0 = pad
__device__ int      g_fill[N_NODES];
__device__ int      g_grouplen[NGROUPS]; // uint4 iterations = ceil(maxfill/4)
__device__ float    g_z[N_NODES];
__device__ float    g_logz[N_NODES];
__device__ unsigned g_tile;              // persistent-kernel work counter

// ---------------- prep kernels ----------------------------------------------
__global__ void k_zero() {
    int i = blockIdx.x * blockDim.x + threadIdx.x;
    int stride = gridDim.x * blockDim.x;
    uint4* p4 = (uint4*)g_pad;
    for (int k = i; k < PAD_ENTRIES / 4; k += stride)
        p4[k] = make_uint4(0u, 0u, 0u, 0u);
    if (i < N_NODES) { g_fill[i] = 0; g_z[i] = 0.f; }
    if (i == 0) g_tile = 0u;
}

__global__ void k_scatter(const int* __restrict__ r0, const int* __restrict__ c0,
                          const float* __restrict__ d0,
                          const int* __restrict__ r1, const int* __restrict__ c1,
                          const float* __restrict__ d1) {
    int k = blockIdx.x * blockDim.x + threadIdx.x;
    if (k >= NNZ_TOT) return;
    int row, col; float w;
    if (k < NNZ_PER) { row = r0[k]; col = c0[k];                   w = d0[k]; }
    else { int j = k - NNZ_PER; row = r1[j]; col = c1[j] + N_CHILD; w = d1[j]; }
    float ew = __expf(w);
    atomicAdd(&g_z[row], ew);
    int j = atomicAdd(&g_fill[row], 1);
    if (j < MAXPAD) {
        int g = row >> 5, lane = row & 31;
        int pos = g * (32 * MAXPAD) + (j >> 2) * 128 + lane * 4 + (j & 3);
        unsigned h = (unsigned)__half_as_ushort(__float2half_rn(ew));
        g_pad[pos] = ((unsigned)col << 16) | h;
    }
}

__global__ void k_finalize() {
    int r = blockIdx.x * blockDim.x + threadIdx.x;
    if (r >= N_NODES) return;
    g_logz[r] = __logf(g_z[r]);
    int f = min(g_fill[r], MAXPAD);
    #pragma unroll
    for (int o = 16; o; o >>= 1)
        f = max(f, __shfl_xor_sync(0xFFFFFFFFu, f, o));
    if ((threadIdx.x & 31) == 0) g_grouplen[r >> 5] = (f + 3) >> 2;
}

// ---------------- main compute kernel ----------------------------------------
// Persistent (148 CTAs, 1/SM) work-stealing 8-sample tiles (512 total).
// exp(ll) stored as half8 (uint4) per merged column in 128 KB smem; every
// SELL entry decode + LDS.128 gather now feeds 8 samples (1.37x fewer L1
// wavefronts per entry-sample than G=4). Inner loop software-pipelined:
// next SELL uint4 prefetched, all four gathers issued before any FMA.
// Group lengths hoisted into registers before the tile loop.
__global__ void __launch_bounds__(NTHREADS, 1)
k_main(const float* __restrict__ ll0, const float* __restrict__ ll1,
       float* __restrict__ out, int ntiles) {
    extern __shared__ uint4 ell[];   // [2 * N_CHILD] half8 entries
    __shared__ int s_tile;
    const int tid  = threadIdx.x;
    const int warp = tid >> 5, lane = tid & 31;

    // tile-invariant per-warp state (hoisted)
    int lenbs[NPASS];
    #pragma unroll
    for (int pass = 0; pass < NPASS; ++pass)
        lenbs[pass] = g_grouplen[warp + pass * NWARPS];

    for (;;) {
        __syncthreads();   // protect ell + s_tile from previous iteration
        if (tid == 0) s_tile = (int)atomicAdd(&g_tile, 1u);
        __syncthreads();
        const int tile = s_tile;
        if (tile >= ntiles) break;

        const long long s0 = (long long)tile * G;

        // exp + pack 8 samples per merged column
        for (int i = tid; i < 2 * N_CHILD; i += NTHREADS) {
            const float* p = (i < N_CHILD) ? (ll0 + s0 * N_CHILD + i)
                                           : (ll1 + s0 * N_CHILD + (i - N_CHILD));
            float e0 = __expf(p[0]);
            float e1 = __expf(p[N_CHILD]);
            float e2 = __expf(p[2 * N_CHILD]);
            float e3 = __expf(p[3 * N_CHILD]);
            float e4 = __expf(p[4 * N_CHILD]);
            float e5 = __expf(p[5 * N_CHILD]);
            float e6 = __expf(p[6 * N_CHILD]);
            float e7 = __expf(p[7 * N_CHILD]);
            __half2 h0 = __floats2half2_rn(e0, e1);
            __half2 h1 = __floats2half2_rn(e2, e3);
            __half2 h2 = __floats2half2_rn(e4, e5);
            __half2 h3 = __floats2half2_rn(e6, e7);
            ell[i] = make_uint4(*(unsigned*)&h0, *(unsigned*)&h1,
                                *(unsigned*)&h2, *(unsigned*)&h3);
        }
        __syncthreads();

        #pragma unroll
        for (int pass = 0; pass < NPASS; ++pass) {   // 2 passes
            const int g    = warp + pass * NWARPS;
            const int lenb = lenbs[pass];
            const uint4* __restrict__ p4 =
                (const uint4*)(g_pad + g * (32 * MAXPAD)) + lane;

            float acc[8];
            #pragma unroll
            for (int q = 0; q < 8; ++q) acc[q] = 0.f;

            uint4 cur = make_uint4(0u, 0u, 0u, 0u);
            if (lenb > 0) cur = __ldg(p4);

            for (int jb = 0; jb < lenb; ++jb) {
                uint4 nxt = make_uint4(0u, 0u, 0u, 0u);
                if (jb + 1 < lenb) nxt = __ldg(&p4[(jb + 1) * 32]);

                // issue all four gathers before consuming any
                uint4 hv0 = ell[cur.x >> 16];
                uint4 hv1 = ell[cur.y >> 16];
                uint4 hv2 = ell[cur.z >> 16];
                uint4 hv3 = ell[cur.w >> 16];
                float w0 = __half2float(__ushort_as_half((unsigned short)(cur.x & 0xFFFFu)));
                float w1 = __half2float(__ushort_as_half((unsigned short)(cur.y & 0xFFFFu)));
                float w2 = __half2float(__ushort_as_half((unsigned short)(cur.z & 0xFFFFu)));
                float w3 = __half2float(__ushort_as_half((unsigned short)(cur.w & 0xFFFFu)));

                #pragma unroll
                for (int h = 0; h < 4; ++h) {
                    unsigned lohi = (h == 0) ? hv0.x : (h == 1) ? hv0.y
                                  : (h == 2) ? hv0.z : hv0.w;
                    float2 v = __half22float2(*(__half2*)&lohi);
                    acc[2*h]   = fmaf(v.x, w0, acc[2*h]);
                    acc[2*h+1] = fmaf(v.y, w0, acc[2*h+1]);
                }
                #pragma unroll
                for (int h = 0; h < 4; ++h) {
                    unsigned lohi = (h == 0) ? hv1.x : (h == 1) ? hv1.y
                                  : (h == 2) ? hv1.z : hv1.w;
                    float2 v = __half22float2(*(__half2*)&lohi);
                    acc[2*h]   = fmaf(v.x, w1, acc[2*h]);
                    acc[2*h+1] = fmaf(v.y, w1, acc[2*h+1]);
                }
                #pragma unroll
                for (int h = 0; h < 4; ++h) {
                    unsigned lohi = (h == 0) ? hv2.x : (h == 1) ? hv2.y
                                  : (h == 2) ? hv2.z : hv2.w;
                    float2 v = __half22float2(*(__half2*)&lohi);
                    acc[2*h]   = fmaf(v.x, w2, acc[2*h]);
                    acc[2*h+1] = fmaf(v.y, w2, acc[2*h+1]);
                }
                #pragma unroll
                for (int h = 0; h < 4; ++h) {
                    unsigned lohi = (h == 0) ? hv3.x : (h == 1) ? hv3.y
                                  : (h == 2) ? hv3.z : hv3.w;
                    float2 v = __half22float2(*(__half2*)&lohi);
                    acc[2*h]   = fmaf(v.x, w3, acc[2*h]);
                    acc[2*h+1] = fmaf(v.y, w3, acc[2*h+1]);
                }

                cur = nxt;
            }

            const int r = g * 32 + lane;
            float lz = g_logz[r];
            float* o = out + s0 * N_NODES + r;
            #pragma unroll
            for (int q = 0; q < 8; ++q)
                o[q * N_NODES] = __logf(acc[q]) - lz;
        }
    }
}

// ---------------- launch ------------------------------------------------------
extern "C" void kernel_launch(void* const* d_in, const int* in_sizes, int n_in,
                              void* d_out, int out_size) {
    const float* ll0 = (const float*)d_in[0];
    const float* ll1 = (const float*)d_in[1];
    const float* w0d = (const float*)d_in[2];
    const float* w1d = (const float*)d_in[3];
    const int*   w0r = (const int*)d_in[4];
    const int*   w0c = (const int*)d_in[5];
    const int*   w1r = (const int*)d_in[6];
    const int*   w1c = (const int*)d_in[7];
    float* out = (float*)d_out;

    const int S = in_sizes[0] / N_CHILD;   // 4096
    const int ntiles = S / G;              // 512

    const int smem_bytes = 2 * N_CHILD * (int)sizeof(uint4);  // 128 KB
    cudaFuncSetAttribute(k_main, cudaFuncAttributeMaxDynamicSharedMemorySize,
                         smem_bytes);

    k_zero<<<384, 256>>>();
    k_scatter<<<(NNZ_TOT + 255) / 256, 256>>>(w0r, w0c, w0d, w1r, w1c, w1d);
    k_finalize<<<(N_NODES + 255) / 256, 256>>>();
    k_main<<<NCTAS, NTHREADS, smem_bytes>>>(ll0, ll1, out, ntiles);
}

// round 10
// speedup vs baseline: 1.0679x; 1.0679x over previous
#include <cuda_runtime.h>
#include <cuda_fp16.h>

// Fixed problem shapes
#define N_NODES   2048
#define N_CHILD   4096
#define NNZ_PER   32768
#define NNZ_TOT   (2 * NNZ_PER)
#define G         4                 // samples per compute block
#define NTHREADS  512
#define NWARPS    (NTHREADS / 32)   // 16
#define NGROUPS   (N_NODES / 32)    // 64 row-groups (one warp each)
#define MAXPAD    96                // group max ~55; margin; mult of 4
#define PAD_ENTRIES (NGROUPS * 32 * MAXPAD)

// ---------------- static device scratch -------------------------------------
// SELL-32, 4-packed: group g, lane l, entry j lives at
//   g*32*MAXPAD + (j>>2)*128 + l*4 + (j&3)
// NOTE: slab is NOT bulk-zeroed; k_finalize zeros exactly the pad slots
// [fill_r, 4*lenb_g) that k_main will read. +128 guard entries allow the
// unconditional prefetch in k_main to read one uint4 row past lenb.
__device__ unsigned g_pad[PAD_ENTRIES + 128];
__device__ int      g_fill[N_NODES];
__device__ int      g_grouplen[NGROUPS];  // uint4 iterations = ceil(maxfill/4)
__device__ float    g_z[N_NODES];
__device__ float    g_logz[N_NODES];

// ---------------- prep kernels ----------------------------------------------
__global__ void k_zero() {
    int i = blockIdx.x * blockDim.x + threadIdx.x;
    if (i < N_NODES) { g_fill[i] = 0; g_z[i] = 0.f; }
}

__global__ void k_scatter(const int* __restrict__ r0, const int* __restrict__ c0,
                          const float* __restrict__ d0,
                          const int* __restrict__ r1, const int* __restrict__ c1,
                          const float* __restrict__ d1) {
    int k = blockIdx.x * blockDim.x + threadIdx.x;
    if (k >= NNZ_TOT) return;
    int row, col; float w;
    if (k < NNZ_PER) { row = r0[k]; col = c0[k];                   w = d0[k]; }
    else { int j = k - NNZ_PER; row = r1[j]; col = c1[j] + N_CHILD; w = d1[j]; }
    float ew = __expf(w);
    atomicAdd(&g_z[row], ew);
    int j = atomicAdd(&g_fill[row], 1);
    if (j < MAXPAD) {
        int g = row >> 5, lane = row & 31;
        int pos = g * (32 * MAXPAD) + (j >> 2) * 128 + lane * 4 + (j & 3);
        unsigned h = (unsigned)__half_as_ushort(__float2half_rn(ew));
        g_pad[pos] = ((unsigned)col << 16) | h;
    }
}

// logz per row, per-group length, and zero ONLY the pad slots k_main reads.
__global__ void k_finalize() {
    int r = blockIdx.x * blockDim.x + threadIdx.x;
    if (r >= N_NODES) return;
    g_logz[r] = __logf(g_z[r]);
    int f = min(g_fill[r], MAXPAD);
    int m = f;
    #pragma unroll
    for (int o = 16; o; o >>= 1)
        m = max(m, __shfl_xor_sync(0xFFFFFFFFu, m, o));
    const int lenb = (m + 3) >> 2;
    const int g = r >> 5, lane = r & 31;
    if (lane == 0) g_grouplen[g] = lenb;
    // zero this row's pad slots [f, 4*lenb)
    for (int j = f; j < 4 * lenb; ++j) {
        int pos = g * (32 * MAXPAD) + (j >> 2) * 128 + lane * 4 + (j & 3);
        g_pad[pos] = 0u;
    }
}

// ---------------- main compute kernel ----------------------------------------
// One block = G=4 samples; exp(ll) as half4 in 64 KB smem -> 3 CTAs/SM,
// 48 warps/SM. One warp = one 32-row group per pass. Software-pipelined:
// next SELL uint4 prefetched UNCONDITIONALLY (guard tail keeps it in-bounds;
// last value never consumed); all 4 random LDS.64 gathers issued before any
// FMA. fp32 register accumulation.
__global__ void __launch_bounds__(NTHREADS, 3)
k_main(const float* __restrict__ ll0, const float* __restrict__ ll1,
       float* __restrict__ out) {
    extern __shared__ uint2 ell[];   // [2 * N_CHILD] half4 entries
    const int tid = threadIdx.x;
    const long long s0 = (long long)blockIdx.x * G;
    const float* p0 = ll0 + s0 * N_CHILD;
    const float* p1 = ll1 + s0 * N_CHILD;

    for (int i = tid; i < N_CHILD; i += NTHREADS) {
        float a0 = __expf(p0[i]);
        float a1 = __expf(p0[i + N_CHILD]);
        float a2 = __expf(p0[i + 2 * N_CHILD]);
        float a3 = __expf(p0[i + 3 * N_CHILD]);
        __half2 h01 = __floats2half2_rn(a0, a1);
        __half2 h23 = __floats2half2_rn(a2, a3);
        ell[i] = make_uint2(*(unsigned*)&h01, *(unsigned*)&h23);

        float b0 = __expf(p1[i]);
        float b1 = __expf(p1[i + N_CHILD]);
        float b2 = __expf(p1[i + 2 * N_CHILD]);
        float b3 = __expf(p1[i + 3 * N_CHILD]);
        __half2 g01 = __floats2half2_rn(b0, b1);
        __half2 g23 = __floats2half2_rn(b2, b3);
        ell[N_CHILD + i] = make_uint2(*(unsigned*)&g01, *(unsigned*)&g23);
    }
    __syncthreads();

    const int warp = tid >> 5, lane = tid & 31;
    #pragma unroll
    for (int pass = 0; pass < NGROUPS / NWARPS; ++pass) {   // 4 passes
        const int g    = warp + pass * NWARPS;
        const int lenb = g_grouplen[g];
        const uint4* __restrict__ p4 =
            (const uint4*)(g_pad + g * (32 * MAXPAD)) + lane;
        float4 acc = make_float4(0.f, 0.f, 0.f, 0.f);

        uint4 cur = __ldg(p4);   // lenb >= 1 always (Poisson(32) rows)

        #pragma unroll 2
        for (int jb = 0; jb < lenb; ++jb) {
            uint4 nxt = __ldg(&p4[(jb + 1) * 32]);   // unconditional; guarded slab

            // issue all four gathers before consuming any
            uint2 hv0 = ell[cur.x >> 16];
            uint2 hv1 = ell[cur.y >> 16];
            uint2 hv2 = ell[cur.z >> 16];
            uint2 hv3 = ell[cur.w >> 16];
            float w0 = __half2float(__ushort_as_half((unsigned short)(cur.x & 0xFFFFu)));
            float w1 = __half2float(__ushort_as_half((unsigned short)(cur.y & 0xFFFFu)));
            float w2 = __half2float(__ushort_as_half((unsigned short)(cur.z & 0xFFFFu)));
            float w3 = __half2float(__ushort_as_half((unsigned short)(cur.w & 0xFFFFu)));

            float2 a01 = __half22float2(*(__half2*)&hv0.x);
            float2 a23 = __half22float2(*(__half2*)&hv0.y);
            acc.x = fmaf(a01.x, w0, acc.x);
            acc.y = fmaf(a01.y, w0, acc.y);
            acc.z = fmaf(a23.x, w0, acc.z);
            acc.w = fmaf(a23.y, w0, acc.w);

            float2 b01 = __half22float2(*(__half2*)&hv1.x);
            float2 b23 = __half22float2(*(__half2*)&hv1.y);
            acc.x = fmaf(b01.x, w1, acc.x);
            acc.y = fmaf(b01.y, w1, acc.y);
            acc.z = fmaf(b23.x, w1, acc.z);
            acc.w = fmaf(b23.y, w1, acc.w);

            float2 c01 = __half22float2(*(__half2*)&hv2.x);
            float2 c23 = __half22float2(*(__half2*)&hv2.y);
            acc.x = fmaf(c01.x, w2, acc.x);
            acc.y = fmaf(c01.y, w2, acc.y);
            acc.z = fmaf(c23.x, w2, acc.z);
            acc.w = fmaf(c23.y, w2, acc.w);

            float2 d01 = __half22float2(*(__half2*)&hv3.x);
            float2 d23 = __half22float2(*(__half2*)&hv3.y);
            acc.x = fmaf(d01.x, w3, acc.x);
            acc.y = fmaf(d01.y, w3, acc.y);
            acc.z = fmaf(d23.x, w3, acc.z);
            acc.w = fmaf(d23.y, w3, acc.w);

            cur = nxt;
        }

        const int r = g * 32 + lane;
        float lz = g_logz[r];
        float* o = out + s0 * N_NODES + r;
        o[0]           = __logf(acc.x) - lz;
        o[N_NODES]     = __logf(acc.y) - lz;
        o[2 * N_NODES] = __logf(acc.z) - lz;
        o[3 * N_NODES] = __logf(acc.w) - lz;
    }
}

// ---------------- launch ------------------------------------------------------
extern "C" void kernel_launch(void* const* d_in, const int* in_sizes, int n_in,
                              void* d_out, int out_size) {
    const float* ll0 = (const float*)d_in[0];
    const float* ll1 = (const float*)d_in[1];
    const float* w0d = (const float*)d_in[2];
    const float* w1d = (const float*)d_in[3];
    const int*   w0r = (const int*)d_in[4];
    const int*   w0c = (const int*)d_in[5];
    const int*   w1r = (const int*)d_in[6];
    const int*   w1c = (const int*)d_in[7];
    float* out = (float*)d_out;

    const int S = in_sizes[0] / N_CHILD;   // 4096
    const int nblocks = S / G;             // 1024

    const int smem_bytes = 2 * N_CHILD * (int)sizeof(uint2);  // 64 KB
    cudaFuncSetAttribute(k_main, cudaFuncAttributeMaxDynamicSharedMemorySize,
                         smem_bytes);

    k_zero<<<(N_NODES + 255) / 256, 256>>>();
    k_scatter<<<(NNZ_TOT + 255) / 256, 256>>>(w0r, w0c, w0d, w1r, w1c, w1d);
    k_finalize<<<(N_NODES + 255) / 256, 256>>>();
    k_main<<<nblocks, NTHREADS, smem_bytes>>>(ll0, ll1, out);
}